// round 15
// baseline (speedup 1.0000x reference)
#include <cuda_runtime.h>
#include <math.h>

// Problem constants
#define TT 1024
#define BB 64
#define DD 256
#define HH 256
#define G4 1024   // 4*H
#define AA 128
#define MM 256

typedef unsigned long long ull;

// ---------------------------------------------------------------------------
// f32x2 packed-FMA helpers (Blackwell fma.rn.f32x2 — 2x fp32 FMA per lane)
// ---------------------------------------------------------------------------
__device__ __forceinline__ void ffma2(ull& d, ull a, ull b) {
    asm("fma.rn.f32x2 %0, %1, %2, %0;" : "+l"(d) : "l"(a), "l"(b));
}
__device__ __forceinline__ ull bcast2(float v) {
    ull r;
    asm("mov.b64 %0, {%1, %1};" : "=l"(r) : "f"(v));
    return r;
}
__device__ __forceinline__ float2 unpk2(ull v) {
    float2 r;
    asm("mov.b64 {%0, %1}, %2;" : "=f"(r.x), "=f"(r.y) : "l"(v));
    return r;
}

// ---------------------------------------------------------------------------
// Device scratch (allocation-free rule: __device__ globals)
// ---------------------------------------------------------------------------
__device__ float d_Gs[TT * G4 * BB];   // stack-LSTM precomputed gates  [t][col][b]
__device__ float d_Gh[TT * G4 * BB];   // hist-LSTM  precomputed gates  [t][col][b]
__device__ float d_Hs[TT * HH * BB];   // stack-LSTM hidden states      [t][k][b]
__device__ float d_Hh2[TT * HH * BB];  // hist-LSTM  hidden states      [t][k][b]
__device__ float d_bsum[TT];           // per-t partial NLL sums
__device__ unsigned g_flags[128];      // per-CTA epoch flags (monotonic across replays)

// ---------------------------------------------------------------------------
// Kernel 1: gate precompute.  G[t][col][b] = emb[ids[b,t]] . Wx[:,col] + bias
//   grid: (1024 row-tiles == t, 16 col-tiles), 256 threads, 64x64 tile, 4x4 micro
// ---------------------------------------------------------------------------
__global__ void __launch_bounds__(256) rnng_gates_kernel(
    const int*   __restrict__ ids,   // [B,T]
    const float* __restrict__ emb,   // [V,256]
    const float* __restrict__ Wx,    // [256,1024]
    const float* __restrict__ bias,  // [1024]
    float*       __restrict__ G)     // [T][1024][64]
{
    const int t  = blockIdx.x;
    const int cb = blockIdx.y * 64;
    const int tid = threadIdx.x;

    __shared__ int   sid[64];
    __shared__ float AsT[16][68];  // [k][b], padded (272B rows -> 16B aligned)
    __shared__ float Bs[16][64];   // [k][c]

    if (tid < 64) sid[tid] = ids[tid * TT + t];
    __syncthreads();

    const int tx = tid & 15, ty = tid >> 4;
    const int lb  = tid >> 2;        // A loader: b
    const int lkq = tid & 3;         // A loader: k-quad
    const int wc  = (tid & 15) * 4;  // B loader: col quad
    const int wk  = tid >> 4;        // B loader: k

    ull acc2[4][2];                  // [row][col-pair]
#pragma unroll
    for (int i = 0; i < 4; i++) { acc2[i][0] = 0ull; acc2[i][1] = 0ull; }

    for (int kb = 0; kb < 256; kb += 16) {
        float4 av = *(const float4*)&emb[sid[lb] * 256 + kb + lkq * 4];
        AsT[lkq * 4 + 0][lb] = av.x;
        AsT[lkq * 4 + 1][lb] = av.y;
        AsT[lkq * 4 + 2][lb] = av.z;
        AsT[lkq * 4 + 3][lb] = av.w;
        *(float4*)&Bs[wk][wc] = *(const float4*)&Wx[(kb + wk) * G4 + cb + wc];
        __syncthreads();
#pragma unroll
        for (int k = 0; k < 16; k++) {
            float4 a = *(const float4*)&AsT[k][ty * 4];
            ulonglong2 bv = *(const ulonglong2*)&Bs[k][tx * 4];
            ull b0 = bv.x, b1 = bv.y;
            float ar[4] = {a.x, a.y, a.z, a.w};
#pragma unroll
            for (int i = 0; i < 4; i++) {
                ull ab = bcast2(ar[i]);
                ffma2(acc2[i][0], ab, b0);
                ffma2(acc2[i][1], ab, b1);
            }
        }
        __syncthreads();
    }

    float accf[4][4];
#pragma unroll
    for (int i = 0; i < 4; i++) {
        float2 p0 = unpk2(acc2[i][0]);
        float2 p1 = unpk2(acc2[i][1]);
        accf[i][0] = p0.x; accf[i][1] = p0.y;
        accf[i][2] = p1.x; accf[i][3] = p1.y;
    }
#pragma unroll
    for (int j = 0; j < 4; j++) {
        int c = cb + tx * 4 + j;
        float bv = bias[c];
        float4 v = make_float4(accf[0][j] + bv, accf[1][j] + bv,
                               accf[2][j] + bv, accf[3][j] + bv);
        *(float4*)&G[(t * G4 + c) * 64 + ty * 4] = v;
    }
}

// ---------------------------------------------------------------------------
// Kernel 2: recurrence. 128 persistent co-resident CTAs,
// blocks 0..63 = stack LSTM, 64..127 = hist LSTM; each CTA owns 4 hidden units.
// Grid barrier = per-CTA release flags (epoch-monotonic, graph-replay safe).
// ---------------------------------------------------------------------------
__device__ __forceinline__ float rnng_sig(float x) { return 1.f / (1.f + __expf(-x)); }

__global__ void __launch_bounds__(256, 1) rnng_recur_kernel(
    const float* __restrict__ Wsh, const float* __restrict__ Whh)
{
    const int blk = blockIdx.x;
    const int L   = blk >> 6;
    const int u0  = (blk & 63) * 4;
    const float* Wh   = L ? Whh : Wsh;
    const float* Gpre = L ? d_Gh : d_Gs;
    float*       Hout = L ? d_Hh2 : d_Hs;

    const int tid = threadIdx.x;
    // GEMM roles: warp = k-chunk of 32, 4 col-quads (== gate), 8 batch-octets
    const int ks = tid >> 5;
    const int cq = (tid >> 3) & 3;   // gate index
    const int b0 = (tid & 7) * 8;
    // update roles
    const int ub = tid & 63;
    const int uq = tid >> 6;

    __shared__ float red[8 * 16 * 64];  // [ks][gate*4+q][b]
    __shared__ unsigned sbase;

    // epoch base: each CTA's flag advances by exactly TT-1 per run -> all equal
    if (tid == 0) sbase = *(volatile unsigned*)&g_flags[blk];
    __syncthreads();
    const unsigned fbase = sbase;

    // Preload this thread's Wh slice into registers (constant over time)
    float Wreg[4][32];
#pragma unroll
    for (int j = 0; j < 4; j++) {
        int gcol = cq * 256 + u0 + j;
#pragma unroll
        for (int kk = 0; kk < 32; kk++)
            Wreg[j][kk] = Wh[(ks * 32 + kk) * 1024 + gcol];
    }

    float cst = 0.f;  // cell state for (ub, unit u0+uq)
    float gp[4];
#pragma unroll
    for (int g = 0; g < 4; g++)
        gp[g] = Gpre[(g * 256 + u0 + uq) * 64 + ub];

    for (int t = 0; t < TT; t++) {
        ull acc2[4][4];   // [gate][batch-pair]
#pragma unroll
        for (int j = 0; j < 4; j++)
#pragma unroll
            for (int i = 0; i < 4; i++) acc2[j][i] = 0ull;

        if (t > 0) {
            const float* hp = Hout + (t - 1) * 256 * 64 + ks * 32 * 64;
#pragma unroll
            for (int kk = 0; kk < 32; kk++) {
                ulonglong2 p0 = *(const ulonglong2*)&hp[kk * 64 + b0];
                ulonglong2 p1 = *(const ulonglong2*)&hp[kk * 64 + b0 + 4];
                ull h2[4] = {p0.x, p0.y, p1.x, p1.y};
#pragma unroll
                for (int j = 0; j < 4; j++) {
                    ull wb = bcast2(Wreg[j][kk]);
#pragma unroll
                    for (int i = 0; i < 4; i++) ffma2(acc2[j][i], wb, h2[i]);
                }
            }
        }

        // store K-split partials (8 floats = 4 ull per gate row)
#pragma unroll
        for (int j = 0; j < 4; j++) {
            ull* rp = (ull*)&red[(ks * 16 + cq * 4 + j) * 64 + b0];
#pragma unroll
            for (int i = 0; i < 4; i++) rp[i] = acc2[j][i];
        }
        __syncthreads();

        // gate math: thread (ub, uq)
        float gv[4];
#pragma unroll
        for (int g = 0; g < 4; g++) {
            float s = gp[g];
#pragma unroll
            for (int k2 = 0; k2 < 8; k2++)
                s += red[(k2 * 16 + g * 4 + uq) * 64 + ub];
            gv[g] = s;
        }
        float iG = rnng_sig(gv[0]);
        float fG = rnng_sig(gv[1]);
        float gG = tanhf(gv[2]);
        float oG = rnng_sig(gv[3]);
        cst = fG * cst + iG * gG;
        Hout[(t * 256 + u0 + uq) * 64 + ub] = oG * tanhf(cst);

        // prefetch next step's precomputed gates (independent of h)
        float gpn[4];
        if (t + 1 < TT) {
#pragma unroll
            for (int g = 0; g < 4; g++)
                gpn[g] = Gpre[((t + 1) * 1024 + g * 256 + u0 + uq) * 64 + ub];
        }

        if (t + 1 < TT) {
            // release: make h(t) visible, then post flag; spin on 128 flags
            __threadfence();
            __syncthreads();
            if (tid == 0)
                *(volatile unsigned*)&g_flags[blk] = fbase + (unsigned)(t + 1);
            if (tid < 128) {
                unsigned target = fbase + (unsigned)(t + 1);
                while ((int)(*(volatile unsigned*)&g_flags[tid] - target) < 0) {}
                __threadfence();
            }
            __syncthreads();
        }
#pragma unroll
        for (int g = 0; g < 4; g++) gp[g] = gpn[g];
    }
}

// ---------------------------------------------------------------------------
// Kernel 3: MLP + log-softmax NLL. One block per t (64 rows).
// x = [buf_emb(256) | h_hist(256) | h_stack(256)]  -> relu(x@W1+b1) @ W2 + b2
// ---------------------------------------------------------------------------
#define MLP_HSM  0                   // Hsm  [256][64]
#define MLP_XST  16384               // XsT  [16][68]
#define MLP_WS   (16384 + 1088)      // Ws   [16][64]
#define MLP_W2S  (16384 + 1088 + 1024)           // W2s [16][128]
#define MLP_LSM  (16384 + 1088 + 1024 + 2048)    // Lsm [64][129]
#define MLP_SMEM ((16384 + 1088 + 1024 + 2048 + 64 * 129) * 4)

__global__ void __launch_bounds__(256) rnng_mlp_kernel(
    const int*   __restrict__ buffer_ids,
    const int*   __restrict__ action_ids,
    const float* __restrict__ word_emb,
    const float* __restrict__ W1, const float* __restrict__ b1,
    const float* __restrict__ W2, const float* __restrict__ b2)
{
    extern __shared__ float sm[];
    float* Hsm = sm + MLP_HSM;   // [m][b]
    float* XsT = sm + MLP_XST;   // [k][b] pad 68
    float* Ws  = sm + MLP_WS;    // [k][c]
    float* W2s = sm + MLP_W2S;   // [k][a]
    float* Lsm = sm + MLP_LSM;   // [b][a] pad 129
    __shared__ int   sbid[64];
    __shared__ float srow[64];

    const int t   = blockIdx.x;
    const int tid = threadIdx.x;
    if (tid < 64) sbid[tid] = buffer_ids[tid * TT + t];
    __syncthreads();

    const int tx = tid & 15, ty = tid >> 4;

    // ---- hidden = relu(x @ W1 + b1), 4 column tiles of 64 ----
    for (int cb = 0; cb < 256; cb += 64) {
        ull acc2[4][2];
#pragma unroll
        for (int i = 0; i < 4; i++) { acc2[i][0] = 0ull; acc2[i][1] = 0ull; }

        for (int kb = 0; kb < 768; kb += 16) {
            // load X^T tile [16][64]
            if (kb < 256) {  // buffer-word embedding gather
                int lb = tid >> 2, lkq = tid & 3;
                float4 v = *(const float4*)&word_emb[sbid[lb] * 256 + kb + lkq * 4];
                XsT[(lkq * 4 + 0) * 68 + lb] = v.x;
                XsT[(lkq * 4 + 1) * 68 + lb] = v.y;
                XsT[(lkq * 4 + 2) * 68 + lb] = v.z;
                XsT[(lkq * 4 + 3) * 68 + lb] = v.w;
            } else {        // shifted LSTM hidden states (zero at t==0)
                int b  = tid & 63;
                int k0 = (tid >> 6) * 4;
                const float* Hsrc = (kb < 512) ? d_Hh2 : d_Hs;
                int hk = (kb < 512) ? (kb - 256) : (kb - 512);
#pragma unroll
                for (int j = 0; j < 4; j++) {
                    float v = (t == 0) ? 0.f
                        : Hsrc[((t - 1) * 256 + hk + k0 + j) * 64 + b];
                    XsT[(k0 + j) * 68 + b] = v;
                }
            }
            // W1 tile
            {
                int wc = (tid & 15) * 4, wk = tid >> 4;
                *(float4*)&Ws[wk * 64 + wc] =
                    *(const float4*)&W1[(kb + wk) * 256 + cb + wc];
            }
            __syncthreads();
#pragma unroll
            for (int k = 0; k < 16; k++) {
                float4 a = *(const float4*)&XsT[k * 68 + ty * 4];
                ulonglong2 bv = *(const ulonglong2*)&Ws[k * 64 + tx * 4];
                float ar[4] = {a.x, a.y, a.z, a.w};
#pragma unroll
                for (int i = 0; i < 4; i++) {
                    ull ab = bcast2(ar[i]);
                    ffma2(acc2[i][0], ab, bv.x);
                    ffma2(acc2[i][1], ab, bv.y);
                }
            }
            __syncthreads();
        }
        // relu + store transposed [m][b]
        float accf[4][4];
#pragma unroll
        for (int i = 0; i < 4; i++) {
            float2 p0 = unpk2(acc2[i][0]);
            float2 p1 = unpk2(acc2[i][1]);
            accf[i][0] = p0.x; accf[i][1] = p0.y;
            accf[i][2] = p1.x; accf[i][3] = p1.y;
        }
#pragma unroll
        for (int j = 0; j < 4; j++) {
            int c = cb + tx * 4 + j;
            float bb = b1[c];
#pragma unroll
            for (int i = 0; i < 4; i++)
                Hsm[c * 64 + ty * 4 + i] = fmaxf(accf[i][j] + bb, 0.f);
        }
    }
    __syncthreads();

    // ---- logits = hidden @ W2 + b2 : 64 x 128, K=256 ----
    {
        const int a0  = (tid & 15) * 8;
        const int lb0 = (tid >> 4) * 4;
        ull acc2[4][4];   // [row][col-pair]
#pragma unroll
        for (int i = 0; i < 4; i++)
#pragma unroll
            for (int j = 0; j < 4; j++) acc2[i][j] = 0ull;

        for (int kb = 0; kb < 256; kb += 16) {
            int wa = (tid & 31) * 4, wk = tid >> 5;
            *(float4*)&W2s[wk * 128 + wa] =
                *(const float4*)&W2[(kb + wk) * 128 + wa];
            *(float4*)&W2s[(wk + 8) * 128 + wa] =
                *(const float4*)&W2[(kb + wk + 8) * 128 + wa];
            __syncthreads();
#pragma unroll
            for (int k = 0; k < 16; k++) {
                float4 hv = *(const float4*)&Hsm[(kb + k) * 64 + lb0];
                ulonglong2 wA = *(const ulonglong2*)&W2s[k * 128 + a0];
                ulonglong2 wB = *(const ulonglong2*)&W2s[k * 128 + a0 + 4];
                ull w2r[4] = {wA.x, wA.y, wB.x, wB.y};
                float h4[4] = {hv.x, hv.y, hv.z, hv.w};
#pragma unroll
                for (int i = 0; i < 4; i++) {
                    ull hb = bcast2(h4[i]);
#pragma unroll
                    for (int jp = 0; jp < 4; jp++) ffma2(acc2[i][jp], hb, w2r[jp]);
                }
            }
            __syncthreads();
        }
#pragma unroll
        for (int i = 0; i < 4; i++) {
#pragma unroll
            for (int jp = 0; jp < 4; jp++) {
                float2 p = unpk2(acc2[i][jp]);
                int c0 = a0 + jp * 2;
                Lsm[(lb0 + i) * 129 + c0]     = p.x + b2[c0];
                Lsm[(lb0 + i) * 129 + c0 + 1] = p.y + b2[c0 + 1];
            }
        }
    }
    __syncthreads();

    // ---- per-row log-softmax NLL ----
    if (tid < 64) {
        const float* L = &Lsm[tid * 129];
        float m = -1e30f;
        for (int a = 0; a < 128; a++) m = fmaxf(m, L[a]);
        float s = 0.f;
        for (int a = 0; a < 128; a++) s += __expf(L[a] - m);
        int act = action_ids[tid * TT + t];
        srow[tid] = -(L[act] - m - __logf(s));
    }
    __syncthreads();
    if (tid == 0) {
        float s = 0.f;
        for (int i = 0; i < 64; i++) s += srow[i];
        d_bsum[t] = s;
    }
}

// ---------------------------------------------------------------------------
// Kernel 4: deterministic final reduction
// ---------------------------------------------------------------------------
__global__ void __launch_bounds__(256) rnng_reduce_kernel(float* __restrict__ out)
{
    __shared__ float sh[256];
    int tid = threadIdx.x;
    float s = 0.f;
    for (int i = tid; i < TT; i += 256) s += d_bsum[i];
    sh[tid] = s;
    __syncthreads();
    for (int st = 128; st > 0; st >>= 1) {
        if (tid < st) sh[tid] += sh[tid + st];
        __syncthreads();
    }
    if (tid == 0) out[0] = sh[0];
}

// ---------------------------------------------------------------------------
// Launch
// ---------------------------------------------------------------------------
extern "C" void kernel_launch(void* const* d_in, const int* in_sizes, int n_in,
                              void* d_out, int out_size)
{
    const int*   stack_ids  = (const int*)d_in[0];
    const int*   buffer_ids = (const int*)d_in[1];
    const int*   action_ids = (const int*)d_in[2];
    const float* word_emb   = (const float*)d_in[3];
    const float* action_emb = (const float*)d_in[4];
    const float* Wsx = (const float*)d_in[5];
    const float* Wsh = (const float*)d_in[6];
    const float* bs  = (const float*)d_in[7];
    const float* Whx = (const float*)d_in[8];
    const float* Whh = (const float*)d_in[9];
    const float* bh  = (const float*)d_in[10];
    const float* W1  = (const float*)d_in[11];
    const float* b1  = (const float*)d_in[12];
    const float* W2  = (const float*)d_in[13];
    const float* b2  = (const float*)d_in[14];
    float* out = (float*)d_out;

    float *Gs, *Gh;
    cudaGetSymbolAddress((void**)&Gs, d_Gs);
    cudaGetSymbolAddress((void**)&Gh, d_Gh);

    cudaFuncSetAttribute(rnng_mlp_kernel,
                         cudaFuncAttributeMaxDynamicSharedMemorySize, MLP_SMEM);

    dim3 ggrid(1024, 16);
    rnng_gates_kernel<<<ggrid, 256>>>(stack_ids,  word_emb,   Wsx, bs, Gs);
    rnng_gates_kernel<<<ggrid, 256>>>(action_ids, action_emb, Whx, bh, Gh);
    rnng_recur_kernel<<<128, 256>>>(Wsh, Whh);
    rnng_mlp_kernel<<<1024, 256, MLP_SMEM>>>(buffer_ids, action_ids, word_emb,
                                             W1, b1, W2, b2);
    rnng_reduce_kernel<<<1, 256>>>(out);
}

// round 16
// speedup vs baseline: 1.9113x; 1.9113x over previous
#include <cuda_runtime.h>
#include <math.h>

// Problem constants
#define TT 1024
#define BB 64
#define DD 256
#define HH 256
#define G4 1024   // 4*H
#define AA 128
#define MM 256

typedef unsigned long long ull;

// ---------------------------------------------------------------------------
// f32x2 packed-FMA helpers (Blackwell fma.rn.f32x2 — 2x fp32 FMA per lane)
// ---------------------------------------------------------------------------
__device__ __forceinline__ void ffma2(ull& d, ull a, ull b) {
    asm("fma.rn.f32x2 %0, %1, %2, %0;" : "+l"(d) : "l"(a), "l"(b));
}
__device__ __forceinline__ ull bcast2(float v) {
    ull r;
    asm("mov.b64 %0, {%1, %1};" : "=l"(r) : "f"(v));
    return r;
}
__device__ __forceinline__ float2 unpk2(ull v) {
    float2 r;
    asm("mov.b64 {%0, %1}, %2;" : "=f"(r.x), "=f"(r.y) : "l"(v));
    return r;
}

// release/acquire barrier primitives (fold fences into the memory ops)
__device__ __forceinline__ void red_release_add1(unsigned* p) {
    asm volatile("red.release.gpu.global.add.u32 [%0], 1;" :: "l"(p) : "memory");
}
__device__ __forceinline__ unsigned ld_acquire(const unsigned* p) {
    unsigned v;
    asm volatile("ld.acquire.gpu.global.u32 %0, [%1];" : "=r"(v) : "l"(p) : "memory");
    return v;
}

// ---------------------------------------------------------------------------
// Device scratch (allocation-free rule: __device__ globals)
// ---------------------------------------------------------------------------
__device__ float d_Gs[TT * G4 * BB];   // stack-LSTM precomputed gates  [t][col][b]
__device__ float d_Gh[TT * G4 * BB];   // hist-LSTM  precomputed gates  [t][col][b]
__device__ float d_Hs[TT * HH * BB];   // stack-LSTM hidden states      [t][k][b]
__device__ float d_Hh2[TT * HH * BB];  // hist-LSTM  hidden states      [t][k][b]
__device__ float d_bsum[TT];           // per-t partial NLL sums
__device__ unsigned g_cnt2[64];        // [0]=stack barrier, [32]=hist barrier (128B apart)
__device__ unsigned g_done2[64];       // per-LSTM completion counters (same padding)

// ---------------------------------------------------------------------------
// Kernel 1: gate precompute.  G[t][col][b] = emb[ids[b,t]] . Wx[:,col] + bias
//   grid: (1024 row-tiles == t, 16 col-tiles), 256 threads, 64x64 tile, 4x4 micro
// ---------------------------------------------------------------------------
__global__ void __launch_bounds__(256) rnng_gates_kernel(
    const int*   __restrict__ ids,   // [B,T]
    const float* __restrict__ emb,   // [V,256]
    const float* __restrict__ Wx,    // [256,1024]
    const float* __restrict__ bias,  // [1024]
    float*       __restrict__ G)     // [T][1024][64]
{
    const int t  = blockIdx.x;
    const int cb = blockIdx.y * 64;
    const int tid = threadIdx.x;

    __shared__ int   sid[64];
    __shared__ float AsT[16][68];  // [k][b], padded
    __shared__ float Bs[16][64];   // [k][c]

    if (tid < 64) sid[tid] = ids[tid * TT + t];
    __syncthreads();

    const int tx = tid & 15, ty = tid >> 4;
    const int lb  = tid >> 2;        // A loader: b
    const int lkq = tid & 3;         // A loader: k-quad
    const int wc  = (tid & 15) * 4;  // B loader: col quad
    const int wk  = tid >> 4;        // B loader: k

    ull acc2[4][2];                  // [row][col-pair]
#pragma unroll
    for (int i = 0; i < 4; i++) { acc2[i][0] = 0ull; acc2[i][1] = 0ull; }

    for (int kb = 0; kb < 256; kb += 16) {
        float4 av = *(const float4*)&emb[sid[lb] * 256 + kb + lkq * 4];
        AsT[lkq * 4 + 0][lb] = av.x;
        AsT[lkq * 4 + 1][lb] = av.y;
        AsT[lkq * 4 + 2][lb] = av.z;
        AsT[lkq * 4 + 3][lb] = av.w;
        *(float4*)&Bs[wk][wc] = *(const float4*)&Wx[(kb + wk) * G4 + cb + wc];
        __syncthreads();
#pragma unroll
        for (int k = 0; k < 16; k++) {
            float4 a = *(const float4*)&AsT[k][ty * 4];
            ulonglong2 bv = *(const ulonglong2*)&Bs[k][tx * 4];
            ull b0 = bv.x, b1 = bv.y;
            float ar[4] = {a.x, a.y, a.z, a.w};
#pragma unroll
            for (int i = 0; i < 4; i++) {
                ull ab = bcast2(ar[i]);
                ffma2(acc2[i][0], ab, b0);
                ffma2(acc2[i][1], ab, b1);
            }
        }
        __syncthreads();
    }

    float accf[4][4];
#pragma unroll
    for (int i = 0; i < 4; i++) {
        float2 p0 = unpk2(acc2[i][0]);
        float2 p1 = unpk2(acc2[i][1]);
        accf[i][0] = p0.x; accf[i][1] = p0.y;
        accf[i][2] = p1.x; accf[i][3] = p1.y;
    }
#pragma unroll
    for (int j = 0; j < 4; j++) {
        int c = cb + tx * 4 + j;
        float bv = bias[c];
        float4 v = make_float4(accf[0][j] + bv, accf[1][j] + bv,
                               accf[2][j] + bv, accf[3][j] + bv);
        *(float4*)&G[(t * G4 + c) * 64 + ty * 4] = v;
    }
}

// ---------------------------------------------------------------------------
// Kernel 2: recurrence. 128 persistent co-resident CTAs,
// blocks 0..63 = stack LSTM, 64..127 = hist LSTM; each CTA owns 4 hidden units.
// TWO independent 64-CTA barriers (one per LSTM): single atomic counter each,
// one poller per CTA, release-red / acquire-ld semantics. Reset at exit.
// ---------------------------------------------------------------------------
__device__ __forceinline__ float rnng_sig(float x) { return 1.f / (1.f + __expf(-x)); }

__global__ void __launch_bounds__(256, 1) rnng_recur_kernel(
    const float* __restrict__ Wsh, const float* __restrict__ Whh)
{
    const int blk = blockIdx.x;
    const int L   = blk >> 6;
    const int u0  = (blk & 63) * 4;
    const float* Wh   = L ? Whh : Wsh;
    const float* Gpre = L ? d_Gh : d_Gs;
    float*       Hout = L ? d_Hh2 : d_Hs;
    unsigned*    cnt  = &g_cnt2[L * 32];
    unsigned*    done = &g_done2[L * 32];

    const int tid = threadIdx.x;
    // GEMM roles: warp = k-chunk of 32, 4 col-quads (== gate), 8 batch-octets
    const int ks = tid >> 5;
    const int cq = (tid >> 3) & 3;   // gate index
    const int b0 = (tid & 7) * 8;
    // update roles
    const int ub = tid & 63;
    const int uq = tid >> 6;

    __shared__ float red[8 * 16 * 64];  // [ks][gate*4+q][b]

    // Preload this thread's Wh slice into registers (constant over time)
    float Wreg[4][32];
#pragma unroll
    for (int j = 0; j < 4; j++) {
        int gcol = cq * 256 + u0 + j;
#pragma unroll
        for (int kk = 0; kk < 32; kk++)
            Wreg[j][kk] = Wh[(ks * 32 + kk) * 1024 + gcol];
    }

    float cst = 0.f;  // cell state for (ub, unit u0+uq)
    float gp[4];
#pragma unroll
    for (int g = 0; g < 4; g++)
        gp[g] = Gpre[(g * 256 + u0 + uq) * 64 + ub];

    for (int t = 0; t < TT; t++) {
        ull acc2[4][4];   // [gate][batch-pair]
#pragma unroll
        for (int j = 0; j < 4; j++)
#pragma unroll
            for (int i = 0; i < 4; i++) acc2[j][i] = 0ull;

        if (t > 0) {
            const float* hp = Hout + (t - 1) * 256 * 64 + ks * 32 * 64;
#pragma unroll
            for (int kk = 0; kk < 32; kk++) {
                ulonglong2 p0 = *(const ulonglong2*)&hp[kk * 64 + b0];
                ulonglong2 p1 = *(const ulonglong2*)&hp[kk * 64 + b0 + 4];
                ull h2[4] = {p0.x, p0.y, p1.x, p1.y};
#pragma unroll
                for (int j = 0; j < 4; j++) {
                    ull wb = bcast2(Wreg[j][kk]);
#pragma unroll
                    for (int i = 0; i < 4; i++) ffma2(acc2[j][i], wb, h2[i]);
                }
            }
        }

        // store K-split partials (8 floats = 4 ull per gate row)
#pragma unroll
        for (int j = 0; j < 4; j++) {
            ull* rp = (ull*)&red[(ks * 16 + cq * 4 + j) * 64 + b0];
#pragma unroll
            for (int i = 0; i < 4; i++) rp[i] = acc2[j][i];
        }
        __syncthreads();

        // gate math: thread (ub, uq)
        float gv[4];
#pragma unroll
        for (int g = 0; g < 4; g++) {
            float s = gp[g];
#pragma unroll
            for (int k2 = 0; k2 < 8; k2++)
                s += red[(k2 * 16 + g * 4 + uq) * 64 + ub];
            gv[g] = s;
        }
        float iG = rnng_sig(gv[0]);
        float fG = rnng_sig(gv[1]);
        float gG = tanhf(gv[2]);
        float oG = rnng_sig(gv[3]);
        cst = fG * cst + iG * gG;
        Hout[(t * 256 + u0 + uq) * 64 + ub] = oG * tanhf(cst);

        // prefetch next step's precomputed gates (independent of h)
        float gpn[4];
        if (t + 1 < TT) {
#pragma unroll
            for (int g = 0; g < 4; g++)
                gpn[g] = Gpre[((t + 1) * 1024 + g * 256 + u0 + uq) * 64 + ub];

            // inter-CTA barrier for this LSTM only (64 CTAs)
            __syncthreads();                 // all h-stores issued, red reusable
            if (tid == 0) {
                red_release_add1(cnt);       // release: h(t) visible before count
                unsigned target = (unsigned)(t + 1) * 64u;
                while (ld_acquire(cnt) < target) {}
            }
            __syncthreads();                 // broadcast acquire to whole CTA
        }
#pragma unroll
        for (int g = 0; g < 4; g++) gp[g] = gpn[g];
    }

    // reset barrier state for the next graph replay (last CTA of each LSTM)
    if (tid == 0) {
        if (atomicAdd(done, 1u) == 63u) {
            *cnt  = 0u;
            *done = 0u;
            __threadfence();
        }
    }
}

// ---------------------------------------------------------------------------
// Kernel 3: MLP + log-softmax NLL. One block per t (64 rows).
// x = [buf_emb(256) | h_hist(256) | h_stack(256)]  -> relu(x@W1+b1) @ W2 + b2
// ---------------------------------------------------------------------------
#define MLP_HSM  0                   // Hsm  [256][64]
#define MLP_XST  16384               // XsT  [16][68]
#define MLP_WS   (16384 + 1088)      // Ws   [16][64]
#define MLP_W2S  (16384 + 1088 + 1024)           // W2s [16][128]
#define MLP_LSM  (16384 + 1088 + 1024 + 2048)    // Lsm [64][129]
#define MLP_SMEM ((16384 + 1088 + 1024 + 2048 + 64 * 129) * 4)

__global__ void __launch_bounds__(256) rnng_mlp_kernel(
    const int*   __restrict__ buffer_ids,
    const int*   __restrict__ action_ids,
    const float* __restrict__ word_emb,
    const float* __restrict__ W1, const float* __restrict__ b1,
    const float* __restrict__ W2, const float* __restrict__ b2)
{
    extern __shared__ float sm[];
    float* Hsm = sm + MLP_HSM;   // [m][b]
    float* XsT = sm + MLP_XST;   // [k][b] pad 68
    float* Ws  = sm + MLP_WS;    // [k][c]
    float* W2s = sm + MLP_W2S;   // [k][a]
    float* Lsm = sm + MLP_LSM;   // [b][a] pad 129
    __shared__ int   sbid[64];
    __shared__ float srow[64];

    const int t   = blockIdx.x;
    const int tid = threadIdx.x;
    if (tid < 64) sbid[tid] = buffer_ids[tid * TT + t];
    __syncthreads();

    const int tx = tid & 15, ty = tid >> 4;

    // ---- hidden = relu(x @ W1 + b1), 4 column tiles of 64 ----
    for (int cb = 0; cb < 256; cb += 64) {
        ull acc2[4][2];
#pragma unroll
        for (int i = 0; i < 4; i++) { acc2[i][0] = 0ull; acc2[i][1] = 0ull; }

        for (int kb = 0; kb < 768; kb += 16) {
            // load X^T tile [16][64]
            if (kb < 256) {  // buffer-word embedding gather
                int lb = tid >> 2, lkq = tid & 3;
                float4 v = *(const float4*)&word_emb[sbid[lb] * 256 + kb + lkq * 4];
                XsT[(lkq * 4 + 0) * 68 + lb] = v.x;
                XsT[(lkq * 4 + 1) * 68 + lb] = v.y;
                XsT[(lkq * 4 + 2) * 68 + lb] = v.z;
                XsT[(lkq * 4 + 3) * 68 + lb] = v.w;
            } else {        // shifted LSTM hidden states (zero at t==0)
                int b  = tid & 63;
                int k0 = (tid >> 6) * 4;
                const float* Hsrc = (kb < 512) ? d_Hh2 : d_Hs;
                int hk = (kb < 512) ? (kb - 256) : (kb - 512);
#pragma unroll
                for (int j = 0; j < 4; j++) {
                    float v = (t == 0) ? 0.f
                        : Hsrc[((t - 1) * 256 + hk + k0 + j) * 64 + b];
                    XsT[(k0 + j) * 68 + b] = v;
                }
            }
            // W1 tile
            {
                int wc = (tid & 15) * 4, wk = tid >> 4;
                *(float4*)&Ws[wk * 64 + wc] =
                    *(const float4*)&W1[(kb + wk) * 256 + cb + wc];
            }
            __syncthreads();
#pragma unroll
            for (int k = 0; k < 16; k++) {
                float4 a = *(const float4*)&XsT[k * 68 + ty * 4];
                ulonglong2 bv = *(const ulonglong2*)&Ws[k * 64 + tx * 4];
                float ar[4] = {a.x, a.y, a.z, a.w};
#pragma unroll
                for (int i = 0; i < 4; i++) {
                    ull ab = bcast2(ar[i]);
                    ffma2(acc2[i][0], ab, bv.x);
                    ffma2(acc2[i][1], ab, bv.y);
                }
            }
            __syncthreads();
        }
        // relu + store transposed [m][b]
        float accf[4][4];
#pragma unroll
        for (int i = 0; i < 4; i++) {
            float2 p0 = unpk2(acc2[i][0]);
            float2 p1 = unpk2(acc2[i][1]);
            accf[i][0] = p0.x; accf[i][1] = p0.y;
            accf[i][2] = p1.x; accf[i][3] = p1.y;
        }
#pragma unroll
        for (int j = 0; j < 4; j++) {
            int c = cb + tx * 4 + j;
            float bb = b1[c];
#pragma unroll
            for (int i = 0; i < 4; i++)
                Hsm[c * 64 + ty * 4 + i] = fmaxf(accf[i][j] + bb, 0.f);
        }
    }
    __syncthreads();

    // ---- logits = hidden @ W2 + b2 : 64 x 128, K=256 ----
    {
        const int a0  = (tid & 15) * 8;
        const int lb0 = (tid >> 4) * 4;
        ull acc2[4][4];   // [row][col-pair]
#pragma unroll
        for (int i = 0; i < 4; i++)
#pragma unroll
            for (int j = 0; j < 4; j++) acc2[i][j] = 0ull;

        for (int kb = 0; kb < 256; kb += 16) {
            int wa = (tid & 31) * 4, wk = tid >> 5;
            *(float4*)&W2s[wk * 128 + wa] =
                *(const float4*)&W2[(kb + wk) * 128 + wa];
            *(float4*)&W2s[(wk + 8) * 128 + wa] =
                *(const float4*)&W2[(kb + wk + 8) * 128 + wa];
            __syncthreads();
#pragma unroll
            for (int k = 0; k < 16; k++) {
                float4 hv = *(const float4*)&Hsm[(kb + k) * 64 + lb0];
                ulonglong2 wA = *(const ulonglong2*)&W2s[k * 128 + a0];
                ulonglong2 wB = *(const ulonglong2*)&W2s[k * 128 + a0 + 4];
                ull w2r[4] = {wA.x, wA.y, wB.x, wB.y};
                float h4[4] = {hv.x, hv.y, hv.z, hv.w};
#pragma unroll
                for (int i = 0; i < 4; i++) {
                    ull hb = bcast2(h4[i]);
#pragma unroll
                    for (int jp = 0; jp < 4; jp++) ffma2(acc2[i][jp], hb, w2r[jp]);
                }
            }
            __syncthreads();
        }
#pragma unroll
        for (int i = 0; i < 4; i++) {
#pragma unroll
            for (int jp = 0; jp < 4; jp++) {
                float2 p = unpk2(acc2[i][jp]);
                int c0 = a0 + jp * 2;
                Lsm[(lb0 + i) * 129 + c0]     = p.x + b2[c0];
                Lsm[(lb0 + i) * 129 + c0 + 1] = p.y + b2[c0 + 1];
            }
        }
    }
    __syncthreads();

    // ---- per-row log-softmax NLL ----
    if (tid < 64) {
        const float* L = &Lsm[tid * 129];
        float m = -1e30f;
        for (int a = 0; a < 128; a++) m = fmaxf(m, L[a]);
        float s = 0.f;
        for (int a = 0; a < 128; a++) s += __expf(L[a] - m);
        int act = action_ids[tid * TT + t];
        srow[tid] = -(L[act] - m - __logf(s));
    }
    __syncthreads();
    if (tid == 0) {
        float s = 0.f;
        for (int i = 0; i < 64; i++) s += srow[i];
        d_bsum[t] = s;
    }
}

// ---------------------------------------------------------------------------
// Kernel 4: deterministic final reduction
// ---------------------------------------------------------------------------
__global__ void __launch_bounds__(256) rnng_reduce_kernel(float* __restrict__ out)
{
    __shared__ float sh[256];
    int tid = threadIdx.x;
    float s = 0.f;
    for (int i = tid; i < TT; i += 256) s += d_bsum[i];
    sh[tid] = s;
    __syncthreads();
    for (int st = 128; st > 0; st >>= 1) {
        if (tid < st) sh[tid] += sh[tid + st];
        __syncthreads();
    }
    if (tid == 0) out[0] = sh[0];
}

// ---------------------------------------------------------------------------
// Launch
// ---------------------------------------------------------------------------
extern "C" void kernel_launch(void* const* d_in, const int* in_sizes, int n_in,
                              void* d_out, int out_size)
{
    const int*   stack_ids  = (const int*)d_in[0];
    const int*   buffer_ids = (const int*)d_in[1];
    const int*   action_ids = (const int*)d_in[2];
    const float* word_emb   = (const float*)d_in[3];
    const float* action_emb = (const float*)d_in[4];
    const float* Wsx = (const float*)d_in[5];
    const float* Wsh = (const float*)d_in[6];
    const float* bs  = (const float*)d_in[7];
    const float* Whx = (const float*)d_in[8];
    const float* Whh = (const float*)d_in[9];
    const float* bh  = (const float*)d_in[10];
    const float* W1  = (const float*)d_in[11];
    const float* b1  = (const float*)d_in[12];
    const float* W2  = (const float*)d_in[13];
    const float* b2  = (const float*)d_in[14];
    float* out = (float*)d_out;

    float *Gs, *Gh;
    cudaGetSymbolAddress((void**)&Gs, d_Gs);
    cudaGetSymbolAddress((void**)&Gh, d_Gh);

    cudaFuncSetAttribute(rnng_mlp_kernel,
                         cudaFuncAttributeMaxDynamicSharedMemorySize, MLP_SMEM);

    dim3 ggrid(1024, 16);
    rnng_gates_kernel<<<ggrid, 256>>>(stack_ids,  word_emb,   Wsx, bs, Gs);
    rnng_gates_kernel<<<ggrid, 256>>>(action_ids, action_emb, Whx, bh, Gh);
    rnng_recur_kernel<<<128, 256>>>(Wsh, Whh);
    rnng_mlp_kernel<<<1024, 256, MLP_SMEM>>>(buffer_ids, action_ids, word_emb,
                                             W1, b1, W2, b2);
    rnng_reduce_kernel<<<1, 256>>>(out);
}